// round 10
// baseline (speedup 1.0000x reference)
#include <cuda_runtime.h>
#include <cuda_bf16.h>
#include <cstdint>
#include <cstddef>

#define N_PIX 4096
#define C_IN  256
#define C_BOT 128
#define NB    4
#define CHUNK 64
#define NCHUNK (N_PIX / CHUNK)
#define LOG2E 1.4426950408889634f

// Scratch (static __device__ arrays — no runtime allocation).
__device__ __nv_bfloat16 g_qt[(size_t)NB * N_PIX * C_BOT];  // [n][c] bf16
__device__ __nv_bfloat16 g_kt[(size_t)NB * N_PIX * C_BOT];  // [n][c] bf16 (pre-scaled log2e)
__device__ __nv_bfloat16 g_vt[(size_t)NB * N_PIX * C_BOT];  // [n][c] bf16
__device__ __nv_bfloat16 g_ot[(size_t)NB * N_PIX * C_BOT];  // [n][c] bf16
__device__ __nv_bfloat16 g_xb[(size_t)NB * C_IN * N_PIX];   // X in bf16
__device__ __nv_bfloat16 g_wq[C_BOT * C_IN];
__device__ __nv_bfloat16 g_wk[C_BOT * C_IN];                // pre-scaled log2e
__device__ __nv_bfloat16 g_wv[C_BOT * C_IN];
__device__ __nv_bfloat16 g_wo[C_IN * C_BOT];

// ---------------------------------------------------------------------------
// low-level helpers
// ---------------------------------------------------------------------------
__device__ __forceinline__ uint32_t swz(uint32_t o) {      // 256B-row tiles
    return o ^ ((o >> 4) & 0x70);
}
__device__ __forceinline__ uint32_t swz128(uint32_t o) {   // 128B-row tiles
    return o ^ ((o >> 3) & 0x70);
}
__device__ __forceinline__ void cp16(uint32_t saddr, const void* g) {
    asm volatile("cp.async.cg.shared.global [%0], [%1], 16;" :: "r"(saddr), "l"(g));
}
#define CP_COMMIT() asm volatile("cp.async.commit_group;" ::: "memory")
#define CP_WAIT0()  asm volatile("cp.async.wait_group 0;"  ::: "memory")

__device__ __forceinline__ void ldm_x4(uint32_t* r, uint32_t a) {
    asm volatile("ldmatrix.sync.aligned.m8n8.x4.shared.b16 {%0,%1,%2,%3}, [%4];"
                 : "=r"(r[0]), "=r"(r[1]), "=r"(r[2]), "=r"(r[3]) : "r"(a));
}
__device__ __forceinline__ void ldm_x4t(uint32_t* r, uint32_t a) {
    asm volatile("ldmatrix.sync.aligned.m8n8.x4.trans.shared.b16 {%0,%1,%2,%3}, [%4];"
                 : "=r"(r[0]), "=r"(r[1]), "=r"(r[2]), "=r"(r[3]) : "r"(a));
}
__device__ __forceinline__ void mma16816(float* d, const uint32_t* a,
                                         uint32_t b0, uint32_t b1) {
    asm volatile(
        "mma.sync.aligned.m16n8k16.row.col.f32.bf16.bf16.f32 "
        "{%0,%1,%2,%3}, {%4,%5,%6,%7}, {%8,%9}, {%0,%1,%2,%3};"
        : "+f"(d[0]), "+f"(d[1]), "+f"(d[2]), "+f"(d[3])
        : "r"(a[0]), "r"(a[1]), "r"(a[2]), "r"(a[3]), "r"(b0), "r"(b1));
}
__device__ __forceinline__ uint32_t pk_bf16x2(float lo, float hi) {
    uint32_t r;
    asm("cvt.rn.bf16x2.f32 %0, %1, %2;" : "=r"(r) : "f"(hi), "f"(lo));
    return r;
}
__device__ __forceinline__ float ex2f(float x) {
    float y;
    asm("ex2.approx.f32 %0, %1;" : "=f"(y) : "f"(x));
    return y;
}

// ---------------------------------------------------------------------------
// One-shot fp32 -> bf16 conversion of X and all weights (Wk scaled by log2e).
// ---------------------------------------------------------------------------
__device__ __forceinline__ void cv4(const float* s, __nv_bfloat16* d, int i) {
    const float4 v = ((const float4*)s)[i];
    uint2 u;
    u.x = pk_bf16x2(v.x, v.y);
    u.y = pk_bf16x2(v.z, v.w);
    ((uint2*)d)[i] = u;
}
__device__ __forceinline__ void cv4s(const float* s, __nv_bfloat16* d, int i, float sc) {
    const float4 v = ((const float4*)s)[i];
    uint2 u;
    u.x = pk_bf16x2(v.x * sc, v.y * sc);
    u.y = pk_bf16x2(v.z * sc, v.w * sc);
    ((uint2*)d)[i] = u;
}

__global__ __launch_bounds__(256)
void convert_bf16(const float* __restrict__ X,
                  const float* __restrict__ Wq, const float* __restrict__ Wk,
                  const float* __restrict__ Wv, const float* __restrict__ Wo,
                  __nv_bfloat16* __restrict__ Xb,
                  __nv_bfloat16* __restrict__ Wqb, __nv_bfloat16* __restrict__ Wkb,
                  __nv_bfloat16* __restrict__ Wvb, __nv_bfloat16* __restrict__ Wob)
{
    const int t = blockIdx.x * 256 + threadIdx.x;
    const int stride = gridDim.x * 256;
    const int NX4 = (NB * C_IN * N_PIX) / 4;
    for (int i = t; i < NX4; i += stride) cv4(X, Xb, i);
    if (t < 8192)       cv4(Wq, Wqb, t);
    else if (t < 16384) cv4s(Wk, Wkb, t - 8192, LOG2E);
    else if (t < 24576) cv4(Wv, Wvb, t - 16384);
    else if (t < 32768) cv4(Wo, Wob, t - 24576);
}

// ---------------------------------------------------------------------------
// Fused flash attention (softmax over i == FA with Q<->K swapped; bounded
// logits -> no running max / rescale). P and l fully register-resident.
// CTA: 64 j-rows x batch. 4 warps; 3 CTAs/SM (64KB smem: K staged in the Q[1]
// buffer and freed after its fragments are hoisted to registers).
// ---------------------------------------------------------------------------
#define SMEM_FLASH 65536   // Q bufs @0,16K; V bufs @32K,48K

__global__ __launch_bounds__(128, 3)
void flash_attn(const __nv_bfloat16* __restrict__ qt,
                const __nv_bfloat16* __restrict__ kt,
                const __nv_bfloat16* __restrict__ vt,
                __nv_bfloat16* __restrict__ ot)
{
    extern __shared__ char sm[];
    const uint32_t smBase = (uint32_t)__cvta_generic_to_shared(sm);
    const uint32_t Qs0 = smBase;
    const uint32_t Vs0 = smBase + 32768;
    const uint32_t Kst = smBase + 16384;   // K staging = Q buffer 1

    const int z  = blockIdx.y;
    const int j0 = blockIdx.x * 64;
    const size_t bstr = (size_t)N_PIX * C_BOT;
    const __nv_bfloat16* qb = qt + (size_t)z * bstr;
    const __nv_bfloat16* kb = kt + (size_t)z * bstr;
    const __nv_bfloat16* vb = vt + (size_t)z * bstr;
    __nv_bfloat16* ob = ot + (size_t)z * bstr;

    const int tid  = threadIdx.x;
    const int lane = tid & 31;
    const int warp = tid >> 5;
    const int g    = lane >> 2;
    const int tig  = lane & 3;

    // K tile (64 x 128 bf16) -> Q buffer 1 (consumed before chunk-1 prefetch)
#pragma unroll
    for (int t = tid; t < 1024; t += 128) {
        const int r = t >> 4, u = t & 15;
        cp16(Kst + swz(r * 256 + u * 16), kb + (size_t)(j0 + r) * C_BOT + u * 8);
    }
    CP_COMMIT();
    // Q0 / V0
#pragma unroll
    for (int t = tid; t < 1024; t += 128) {
        const int r = t >> 4, u = t & 15;
        cp16(Qs0 + swz(r * 256 + u * 16), qb + (size_t)r * C_BOT + u * 8);
        cp16(Vs0 + swz(r * 256 + u * 16), vb + (size_t)r * C_BOT + u * 8);
    }
    CP_COMMIT();
    CP_WAIT0();
    __syncthreads();

    // hoist K A-fragments (8 k-slices of 16) — K smem is dead afterwards
    uint32_t ka[8][4];
    {
        const uint32_t row = warp * 16 + (lane & 15);
        const uint32_t cb  = ((uint32_t)lane >> 4) * 16;
#pragma unroll
        for (int s = 0; s < 8; s++)
            ldm_x4(ka[s], Kst + swz(row * 256 + cb + s * 32));
    }

    float accO[16][4];
#pragma unroll
    for (int ct = 0; ct < 16; ct++)
#pragma unroll
        for (int e = 0; e < 4; e++) accO[ct][e] = 0.0f;
    float l0 = 0.0f, l1 = 0.0f;

    const uint32_t qrow = (((uint32_t)lane >> 4) & 1) * 8 + (lane & 7);
    const uint32_t qsel = (((uint32_t)lane >> 3) & 1) * 16;
    const uint32_t vrow = (uint32_t)(lane & 15);
    const uint32_t vsel = (((uint32_t)lane >> 4) & 1) * 16;

    for (int n = 0; n < NCHUNK; n++) {
        const uint32_t Qc = Qs0 + (uint32_t)(n & 1) * 16384;
        const uint32_t Vc = Vs0 + (uint32_t)(n & 1) * 16384;

        CP_WAIT0();
        __syncthreads();   // (at n=0 this also fences the ka hoist vs QB reuse)

        if (n + 1 < NCHUNK) {
            const uint32_t Qn = Qs0 + (uint32_t)((n + 1) & 1) * 16384;
            const uint32_t Vn = Vs0 + (uint32_t)((n + 1) & 1) * 16384;
            const __nv_bfloat16* qsrc = qb + (size_t)(n + 1) * CHUNK * C_BOT;
            const __nv_bfloat16* vsrc = vb + (size_t)(n + 1) * CHUNK * C_BOT;
#pragma unroll
            for (int t = tid; t < 1024; t += 128) {
                const int r = t >> 4, u = t & 15;
                cp16(Qn + swz(r * 256 + u * 16), qsrc + (size_t)r * C_BOT + u * 8);
                cp16(Vn + swz(r * 256 + u * 16), vsrc + (size_t)r * C_BOT + u * 8);
            }
            CP_COMMIT();
        }

        // T = K . Q^T  (16 j x 64 i per warp); k pre-scaled by log2e
        float tacc[8][4];
#pragma unroll
        for (int n8 = 0; n8 < 8; n8++)
#pragma unroll
            for (int e = 0; e < 4; e++) tacc[n8][e] = 0.0f;
#pragma unroll
        for (int k = 0; k < 8; k++) {
#pragma unroll
            for (int n8p = 0; n8p < 4; n8p++) {
                uint32_t b[4];
                ldm_x4(b, Qc + swz((n8p * 16 + qrow) * 256 + k * 32 + qsel));
                mma16816(tacc[2 * n8p],     ka[k], b[0], b[1]);
                mma16816(tacc[2 * n8p + 1], ka[k], b[2], b[3]);
            }
        }

        // exp via ex2 (logits pre-scaled), rowsum, pack P
        uint32_t pa[4][4];
#pragma unroll
        for (int n8 = 0; n8 < 8; n8++) {
            const float e0 = ex2f(tacc[n8][0]);
            const float e1 = ex2f(tacc[n8][1]);
            const float e2 = ex2f(tacc[n8][2]);
            const float e3 = ex2f(tacc[n8][3]);
            l0 += e0 + e1;
            l1 += e2 + e3;
            const int s = n8 >> 1, h = (n8 & 1) * 2;
            pa[s][h]     = pk_bf16x2(e0, e1);
            pa[s][h + 1] = pk_bf16x2(e2, e3);
        }

        // O += P . V  (16 j x 128 c per warp)
#pragma unroll
        for (int s = 0; s < 4; s++) {
#pragma unroll
            for (int ctp = 0; ctp < 8; ctp++) {
                uint32_t b[4];
                ldm_x4t(b, Vc + swz((s * 16 + vrow) * 256 + ctp * 32 + vsel));
                mma16816(accO[2 * ctp],     pa[s], b[0], b[1]);
                mma16816(accO[2 * ctp + 1], pa[s], b[2], b[3]);
            }
        }
    }

    // epilogue: reduce l over quad, normalize, stage, write bf16
    l0 += __shfl_xor_sync(0xffffffffu, l0, 1);
    l0 += __shfl_xor_sync(0xffffffffu, l0, 2);
    l1 += __shfl_xor_sync(0xffffffffu, l1, 1);
    l1 += __shfl_xor_sync(0xffffffffu, l1, 2);
    const float inv0 = 1.0f / l0;
    const float inv1 = 1.0f / l1;

    __syncthreads();
    float* Os = (float*)sm;          // 64 x 128 fp32 staging (32KB)
    const int r0 = warp * 16 + g;
#pragma unroll
    for (int ct = 0; ct < 16; ct++) {
        *(float2*)&Os[r0 * 128 + ct * 8 + tig * 2] =
            make_float2(accO[ct][0] * inv0, accO[ct][1] * inv0);
        *(float2*)&Os[(r0 + 8) * 128 + ct * 8 + tig * 2] =
            make_float2(accO[ct][2] * inv1, accO[ct][3] * inv1);
    }
    __syncthreads();
#pragma unroll
    for (int t = tid; t < 64 * 16; t += 128) {
        const int r = t >> 4, c8 = t & 15;
        const float4 v0 = ((const float4*)(Os + r * 128))[c8 * 2];
        const float4 v1 = ((const float4*)(Os + r * 128))[c8 * 2 + 1];
        uint4 u;
        u.x = pk_bf16x2(v0.x, v0.y);
        u.y = pk_bf16x2(v0.z, v0.w);
        u.z = pk_bf16x2(v1.x, v1.y);
        u.w = pk_bf16x2(v1.z, v1.w);
        ((uint4*)(ob + (size_t)(j0 + r) * C_BOT))[c8] = u;
    }
}

// ---------------------------------------------------------------------------
// Fused QKV projection, all-bf16, cp.async double-buffered (round-7 proven).
// bk bias scaled by log2e to match pre-scaled Wk.
// ---------------------------------------------------------------------------
#define QKVB 32768

__global__ __launch_bounds__(128, 2)
void qkv_gemm(const __nv_bfloat16* __restrict__ Xb,
              const __nv_bfloat16* __restrict__ Wqb, const float* __restrict__ bq,
              const __nv_bfloat16* __restrict__ Wkb, const float* __restrict__ bk,
              const __nv_bfloat16* __restrict__ Wvb, const float* __restrict__ bv,
              __nv_bfloat16* __restrict__ qt, __nv_bfloat16* __restrict__ kt,
              __nv_bfloat16* __restrict__ vt)
{
    extern __shared__ char qsm[];
    const uint32_t sb = (uint32_t)__cvta_generic_to_shared(qsm);

    const int z  = blockIdx.z;
    const int m0 = blockIdx.y * 64;
    const int n0 = blockIdx.x * 64;
    const __nv_bfloat16* Xz = Xb + (size_t)z * C_IN * N_PIX;
    const __nv_bfloat16* Wp[3] = {Wqb, Wkb, Wvb};
    const float* bp[3] = {bq, bk, bv};
    __nv_bfloat16* outp[3] = {qt + (size_t)z * N_PIX * C_BOT,
                              kt + (size_t)z * N_PIX * C_BOT,
                              vt + (size_t)z * N_PIX * C_BOT};

    const int tid  = threadIdx.x;
    const int lane = tid & 31;
    const int warp = tid >> 5;
    const int g    = lane >> 2;
    const int tig  = lane & 3;

    auto prefetch = [&](int kc) {
        const uint32_t b = sb + (uint32_t)(kc & 1) * QKVB;
        const int k0 = kc * 64;
#pragma unroll
        for (int p = 0; p < 3; p++)
#pragma unroll
            for (int t = tid; t < 512; t += 128) {
                const int r = t >> 3, u = t & 7;
                cp16(b + p * 8192 + swz128(r * 128 + u * 16),
                     Wp[p] + (size_t)(m0 + r) * C_IN + k0 + u * 8);
            }
#pragma unroll
        for (int t = tid; t < 512; t += 128) {
            const int r = t >> 3, u = t & 7;
            cp16(b + 24576 + swz128(r * 128 + u * 16),
                 Xz + (size_t)(k0 + r) * N_PIX + n0 + u * 8);
        }
        CP_COMMIT();
    };

    prefetch(0);

    float acc[3][8][4];
#pragma unroll
    for (int p = 0; p < 3; p++)
#pragma unroll
        for (int n8 = 0; n8 < 8; n8++)
#pragma unroll
            for (int e = 0; e < 4; e++) acc[p][n8][e] = 0.0f;

    const uint32_t arow = (warp * 16 + (lane & 15)) * 128 + (((uint32_t)lane >> 4) & 1) * 16;
    const uint32_t xrow = (uint32_t)(lane & 15) * 128;
    const uint32_t xsel = (((uint32_t)lane >> 4) & 1) * 16;

    for (int kc = 0; kc < 4; kc++) {
        CP_WAIT0();
        __syncthreads();
        if (kc < 3) prefetch(kc + 1);

        const uint32_t W0 = sb + (uint32_t)(kc & 1) * QKVB;
        const uint32_t X0 = W0 + 24576;
#pragma unroll
        for (int ks = 0; ks < 4; ks++) {
            uint32_t a[3][4];
#pragma unroll
            for (int p = 0; p < 3; p++)
                ldm_x4(a[p], W0 + p * 8192 + swz128(arow + ks * 32));
#pragma unroll
            for (int n8p = 0; n8p < 4; n8p++) {
                uint32_t b[4];
                ldm_x4t(b, X0 + swz128((ks * 16) * 128 + xrow + n8p * 32 + xsel));
#pragma unroll
                for (int p = 0; p < 3; p++) {
                    mma16816(acc[p][2 * n8p],     a[p], b[0], b[1]);
                    mma16816(acc[p][2 * n8p + 1], a[p], b[2], b[3]);
                }
            }
        }
    }

    __syncthreads();
    float* Cs = (float*)qsm;   // [64][68]
#pragma unroll
    for (int p = 0; p < 3; p++) {
#pragma unroll
        for (int n8 = 0; n8 < 8; n8++) {
            const int rr = warp * 16 + g;
            const int cc = n8 * 8 + tig * 2;
            Cs[rr * 68 + cc]           = acc[p][n8][0];
            Cs[rr * 68 + cc + 1]       = acc[p][n8][1];
            Cs[(rr + 8) * 68 + cc]     = acc[p][n8][2];
            Cs[(rr + 8) * 68 + cc + 1] = acc[p][n8][3];
        }
        __syncthreads();
        const float bsc = (p == 1) ? LOG2E : 1.0f;
#pragma unroll 4
        for (int idx = tid; idx < 64 * 64; idx += 128) {
            const int r = idx & 63;   // m (channel)
            const int c = idx >> 6;   // n (pixel)
            const float v = Cs[r * 68 + c] + bp[p][m0 + r] * bsc;
            outp[p][(size_t)(n0 + c) * C_BOT + m0 + r] = __float2bfloat16(v);
        }
        __syncthreads();
    }
}

// ---------------------------------------------------------------------------
// Final projection (round-7 proven): y = gamma*(Wo . O + bo) + X.
// ---------------------------------------------------------------------------
__global__ __launch_bounds__(128)
void final_gemm(const __nv_bfloat16* __restrict__ Wob,
                const __nv_bfloat16* __restrict__ ot,
                float* __restrict__ out, const float* __restrict__ bo,
                const float* __restrict__ gammap, const float* __restrict__ X)
{
    __shared__ char buf[32768];
    const uint32_t sA = (uint32_t)__cvta_generic_to_shared(buf);
    const uint32_t sB = sA + 16384;
    float* Cs = (float*)buf;

    const int z  = blockIdx.z;
    const int o0 = blockIdx.y * 64;
    const int n0 = blockIdx.x * 64;
    const __nv_bfloat16* Ob = ot + (size_t)z * N_PIX * C_BOT;
    float* outb = out + (size_t)z * C_IN * N_PIX;
    const float* Xb = X + (size_t)z * C_IN * N_PIX;

    const int tid  = threadIdx.x;
    const int lane = tid & 31;
    const int warp = tid >> 5;
    const int wm = warp >> 1, wn = warp & 1;
    const int g  = lane >> 2, tig = lane & 3;

#pragma unroll
    for (int t = tid; t < 1024; t += 128) {
        const int r = t >> 4, u = t & 15;
        cp16(sA + swz(r * 256 + u * 16), Wob + (size_t)(o0 + r) * C_BOT + u * 8);
        cp16(sB + swz(r * 256 + u * 16), Ob + (size_t)(n0 + r) * C_BOT + u * 8);
    }
    CP_COMMIT();
    CP_WAIT0();
    __syncthreads();

    uint32_t a[2][8][4];
    {
        const uint32_t cb = (((uint32_t)lane >> 4) & 1) * 16;
#pragma unroll
        for (int im = 0; im < 2; im++)
#pragma unroll
            for (int ks = 0; ks < 8; ks++)
                ldm_x4(a[im][ks],
                       sA + swz((wm * 32 + im * 16 + (lane & 15)) * 256 + ks * 32 + cb));
    }

    float acc[2][4][4];
#pragma unroll
    for (int im = 0; im < 2; im++)
#pragma unroll
        for (int n8 = 0; n8 < 4; n8++)
#pragma unroll
            for (int e = 0; e < 4; e++) acc[im][n8][e] = 0.0f;

    {
        const uint32_t brow = (uint32_t)(lane & 15);
        const uint32_t bsel = (((uint32_t)lane >> 4) & 1) * 16;
#pragma unroll
        for (int ks = 0; ks < 8; ks++) {
#pragma unroll
            for (int n8p = 0; n8p < 2; n8p++) {
                uint32_t b[4];
                ldm_x4(b, sB + swz((wn * 32 + n8p * 16 + brow) * 256 + ks * 32 + bsel));
                mma16816(acc[0][2 * n8p],     a[0][ks], b[0], b[2]);
                mma16816(acc[0][2 * n8p + 1], a[0][ks], b[1], b[3]);
                mma16816(acc[1][2 * n8p],     a[1][ks], b[0], b[2]);
                mma16816(acc[1][2 * n8p + 1], a[1][ks], b[1], b[3]);
            }
        }
    }

    __syncthreads();
#pragma unroll
    for (int im = 0; im < 2; im++)
#pragma unroll
        for (int n8 = 0; n8 < 4; n8++) {
            const int rr = wm * 32 + im * 16 + g;
            const int cc = wn * 32 + n8 * 8 + tig * 2;
            Cs[rr * 68 + cc]           = acc[im][n8][0];
            Cs[rr * 68 + cc + 1]       = acc[im][n8][1];
            Cs[(rr + 8) * 68 + cc]     = acc[im][n8][2];
            Cs[(rr + 8) * 68 + cc + 1] = acc[im][n8][3];
        }
    __syncthreads();

    const float gm = gammap[0];
#pragma unroll
    for (int t = tid; t < 64 * 16; t += 128) {
        const int r = t >> 4, c4 = t & 15;
        const size_t off = (size_t)(o0 + r) * N_PIX + n0 + c4 * 4;
        const float4 xv = *(const float4*)&Xb[off];
        const float b = bo[o0 + r];
        float4 o;
        o.x = gm * (Cs[r * 68 + c4 * 4 + 0] + b) + xv.x;
        o.y = gm * (Cs[r * 68 + c4 * 4 + 1] + b) + xv.y;
        o.z = gm * (Cs[r * 68 + c4 * 4 + 2] + b) + xv.z;
        o.w = gm * (Cs[r * 68 + c4 * 4 + 3] + b) + xv.w;
        *(float4*)&outb[off] = o;
    }
}

extern "C" void kernel_launch(void* const* d_in, const int* in_sizes, int n_in,
                              void* d_out, int out_size)
{
    const float* X     = (const float*)d_in[0];
    const float* Wq    = (const float*)d_in[1];
    const float* bq    = (const float*)d_in[2];
    const float* Wk    = (const float*)d_in[3];
    const float* bk    = (const float*)d_in[4];
    const float* Wv    = (const float*)d_in[5];
    const float* bv    = (const float*)d_in[6];
    const float* Wo    = (const float*)d_in[7];
    const float* bo    = (const float*)d_in[8];
    const float* gamma = (const float*)d_in[9];
    float* out = (float*)d_out;

    __nv_bfloat16 *qt, *kt, *vt, *ot, *xb, *wq, *wk, *wv, *wo;
    cudaGetSymbolAddress((void**)&qt, g_qt);
    cudaGetSymbolAddress((void**)&kt, g_kt);
    cudaGetSymbolAddress((void**)&vt, g_vt);
    cudaGetSymbolAddress((void**)&ot, g_ot);
    cudaGetSymbolAddress((void**)&xb, g_xb);
    cudaGetSymbolAddress((void**)&wq, g_wq);
    cudaGetSymbolAddress((void**)&wk, g_wk);
    cudaGetSymbolAddress((void**)&wv, g_wv);
    cudaGetSymbolAddress((void**)&wo, g_wo);

    cudaFuncSetAttribute(flash_attn, cudaFuncAttributeMaxDynamicSharedMemorySize,
                         SMEM_FLASH);
    cudaFuncSetAttribute(qkv_gemm, cudaFuncAttributeMaxDynamicSharedMemorySize,
                         2 * QKVB);

    // 0) one-shot bf16 conversion of X and weights (Wk pre-scaled by log2e)
    convert_bf16<<<2048, 256>>>(X, Wq, Wk, Wv, Wo, xb, wq, wk, wv, wo);

    // 1) fused QKV -> transposed bf16 [n][c]
    qkv_gemm<<<dim3(N_PIX / 64, C_BOT / 64, NB), 128, 2 * QKVB>>>(
        xb, wq, bq, wk, bk, wv, bv, qt, kt, vt);

    // 2) fused attention -> ot bf16 [n][c]
    flash_attn<<<dim3(N_PIX / 64, NB), 128, SMEM_FLASH>>>(qt, kt, vt, ot);

    // 3) y = gamma*(Wo . O + bo) + X
    final_gemm<<<dim3(N_PIX / 64, C_IN / 64, NB), 128>>>(
        wo, ot, out, bo, gamma, X);
}

// round 11
// speedup vs baseline: 1.1012x; 1.1012x over previous
#include <cuda_runtime.h>
#include <cuda_bf16.h>
#include <cstdint>
#include <cstddef>

#define N_PIX 4096
#define C_IN  256
#define C_BOT 128
#define NB    4
#define CHUNK 64
#define NCHUNK (N_PIX / CHUNK)
#define LOG2E 1.4426950408889634f

// Scratch (static __device__ arrays — no runtime allocation).
__device__ __nv_bfloat16 g_qt[(size_t)NB * N_PIX * C_BOT];  // [n][c] bf16
__device__ __nv_bfloat16 g_kt[(size_t)NB * N_PIX * C_BOT];  // [n][c] bf16 (pre-scaled log2e)
__device__ __nv_bfloat16 g_vt[(size_t)NB * N_PIX * C_BOT];  // [n][c] bf16
__device__ __nv_bfloat16 g_ot[(size_t)NB * N_PIX * C_BOT];  // [n][c] bf16
__device__ __nv_bfloat16 g_xb[(size_t)NB * C_IN * N_PIX];   // X in bf16
__device__ __nv_bfloat16 g_wq[C_BOT * C_IN];
__device__ __nv_bfloat16 g_wk[C_BOT * C_IN];                // pre-scaled log2e
__device__ __nv_bfloat16 g_wv[C_BOT * C_IN];
__device__ __nv_bfloat16 g_wo[C_IN * C_BOT];

// ---------------------------------------------------------------------------
// low-level helpers
// ---------------------------------------------------------------------------
__device__ __forceinline__ uint32_t swz(uint32_t o) {      // 256B-row tiles
    return o ^ ((o >> 4) & 0x70);
}
__device__ __forceinline__ uint32_t swz128(uint32_t o) {   // 128B-row tiles
    return o ^ ((o >> 3) & 0x70);
}
__device__ __forceinline__ void cp16(uint32_t saddr, const void* g) {
    asm volatile("cp.async.cg.shared.global [%0], [%1], 16;" :: "r"(saddr), "l"(g));
}
#define CP_COMMIT() asm volatile("cp.async.commit_group;" ::: "memory")
#define CP_WAIT0()  asm volatile("cp.async.wait_group 0;"  ::: "memory")

__device__ __forceinline__ void ldm_x4(uint32_t* r, uint32_t a) {
    asm volatile("ldmatrix.sync.aligned.m8n8.x4.shared.b16 {%0,%1,%2,%3}, [%4];"
                 : "=r"(r[0]), "=r"(r[1]), "=r"(r[2]), "=r"(r[3]) : "r"(a));
}
__device__ __forceinline__ void ldm_x4t(uint32_t* r, uint32_t a) {
    asm volatile("ldmatrix.sync.aligned.m8n8.x4.trans.shared.b16 {%0,%1,%2,%3}, [%4];"
                 : "=r"(r[0]), "=r"(r[1]), "=r"(r[2]), "=r"(r[3]) : "r"(a));
}
__device__ __forceinline__ void mma16816(float* d, const uint32_t* a,
                                         uint32_t b0, uint32_t b1) {
    asm volatile(
        "mma.sync.aligned.m16n8k16.row.col.f32.bf16.bf16.f32 "
        "{%0,%1,%2,%3}, {%4,%5,%6,%7}, {%8,%9}, {%0,%1,%2,%3};"
        : "+f"(d[0]), "+f"(d[1]), "+f"(d[2]), "+f"(d[3])
        : "r"(a[0]), "r"(a[1]), "r"(a[2]), "r"(a[3]), "r"(b0), "r"(b1));
}
__device__ __forceinline__ uint32_t pk_bf16x2(float lo, float hi) {
    uint32_t r;
    asm("cvt.rn.bf16x2.f32 %0, %1, %2;" : "=r"(r) : "f"(hi), "f"(lo));
    return r;
}
__device__ __forceinline__ float ex2f(float x) {
    float y;
    asm("ex2.approx.f32 %0, %1;" : "=f"(y) : "f"(x));
    return y;
}

// ---------------------------------------------------------------------------
// One-shot fp32 -> bf16 conversion of X and all weights (Wk scaled by log2e).
// ---------------------------------------------------------------------------
__device__ __forceinline__ void cv4(const float* s, __nv_bfloat16* d, int i) {
    const float4 v = ((const float4*)s)[i];
    uint2 u;
    u.x = pk_bf16x2(v.x, v.y);
    u.y = pk_bf16x2(v.z, v.w);
    ((uint2*)d)[i] = u;
}
__device__ __forceinline__ void cv4s(const float* s, __nv_bfloat16* d, int i, float sc) {
    const float4 v = ((const float4*)s)[i];
    uint2 u;
    u.x = pk_bf16x2(v.x * sc, v.y * sc);
    u.y = pk_bf16x2(v.z * sc, v.w * sc);
    ((uint2*)d)[i] = u;
}

__global__ __launch_bounds__(256)
void convert_bf16(const float* __restrict__ X,
                  const float* __restrict__ Wq, const float* __restrict__ Wk,
                  const float* __restrict__ Wv, const float* __restrict__ Wo,
                  __nv_bfloat16* __restrict__ Xb,
                  __nv_bfloat16* __restrict__ Wqb, __nv_bfloat16* __restrict__ Wkb,
                  __nv_bfloat16* __restrict__ Wvb, __nv_bfloat16* __restrict__ Wob)
{
    const int t = blockIdx.x * 256 + threadIdx.x;
    const int stride = gridDim.x * 256;
    const int NX4 = (NB * C_IN * N_PIX) / 4;
    for (int i = t; i < NX4; i += stride) cv4(X, Xb, i);
    if (t < 8192)       cv4(Wq, Wqb, t);
    else if (t < 16384) cv4s(Wk, Wkb, t - 8192, LOG2E);
    else if (t < 24576) cv4(Wv, Wvb, t - 16384);
    else if (t < 32768) cv4(Wo, Wob, t - 24576);
}

// ---------------------------------------------------------------------------
// Fused flash attention (softmax over i == FA with Q<->K swapped; bounded
// logits -> no running max / rescale). P and l fully register-resident.
// CTA: 64 j-rows x batch. 4 warps; 2 CTAs/SM; ldmatrix.x4 everywhere.
// (Round-7 proven configuration; exp via ex2 on pre-scaled logits.)
// ---------------------------------------------------------------------------
#define SM_K  0
#define SM_Q  16384
#define SM_V  49152
#define SMEM_FLASH 81920

__global__ __launch_bounds__(128, 2)
void flash_attn(const __nv_bfloat16* __restrict__ qt,
                const __nv_bfloat16* __restrict__ kt,
                const __nv_bfloat16* __restrict__ vt,
                __nv_bfloat16* __restrict__ ot)
{
    extern __shared__ char sm[];
    const uint32_t smBase = (uint32_t)__cvta_generic_to_shared(sm);
    const uint32_t Ks  = smBase + SM_K;
    const uint32_t Qs0 = smBase + SM_Q;
    const uint32_t Vs0 = smBase + SM_V;

    const int z  = blockIdx.y;
    const int j0 = blockIdx.x * 64;
    const size_t bstr = (size_t)N_PIX * C_BOT;
    const __nv_bfloat16* qb = qt + (size_t)z * bstr;
    const __nv_bfloat16* kb = kt + (size_t)z * bstr;
    const __nv_bfloat16* vb = vt + (size_t)z * bstr;
    __nv_bfloat16* ob = ot + (size_t)z * bstr;

    const int tid  = threadIdx.x;
    const int lane = tid & 31;
    const int warp = tid >> 5;
    const int g    = lane >> 2;
    const int tig  = lane & 3;

    // K tile (64 x 128 bf16), resident whole kernel
#pragma unroll
    for (int t = tid; t < 1024; t += 128) {
        const int r = t >> 4, u = t & 15;
        cp16(Ks + swz(r * 256 + u * 16), kb + (size_t)(j0 + r) * C_BOT + u * 8);
    }
    CP_COMMIT();
#pragma unroll
    for (int t = tid; t < 1024; t += 128) {
        const int r = t >> 4, u = t & 15;
        cp16(Qs0 + swz(r * 256 + u * 16), qb + (size_t)r * C_BOT + u * 8);
        cp16(Vs0 + swz(r * 256 + u * 16), vb + (size_t)r * C_BOT + u * 8);
    }
    CP_COMMIT();
    CP_WAIT0();
    __syncthreads();

    // hoist K A-fragments (8 k-slices of 16) — never change
    uint32_t ka[8][4];
    {
        const uint32_t row = warp * 16 + (lane & 15);
        const uint32_t cb  = ((uint32_t)lane >> 4) * 16;
#pragma unroll
        for (int s = 0; s < 8; s++)
            ldm_x4(ka[s], Ks + swz(row * 256 + cb + s * 32));
    }

    float accO[16][4];
#pragma unroll
    for (int ct = 0; ct < 16; ct++)
#pragma unroll
        for (int e = 0; e < 4; e++) accO[ct][e] = 0.0f;
    float l0 = 0.0f, l1 = 0.0f;

    const uint32_t qrow = (((uint32_t)lane >> 4) & 1) * 8 + (lane & 7);
    const uint32_t qsel = (((uint32_t)lane >> 3) & 1) * 16;
    const uint32_t vrow = (uint32_t)(lane & 15);
    const uint32_t vsel = (((uint32_t)lane >> 4) & 1) * 16;

    for (int n = 0; n < NCHUNK; n++) {
        const uint32_t Qc = Qs0 + (uint32_t)(n & 1) * 16384;
        const uint32_t Vc = Vs0 + (uint32_t)(n & 1) * 16384;

        CP_WAIT0();
        __syncthreads();

        if (n + 1 < NCHUNK) {
            const uint32_t Qn = Qs0 + (uint32_t)((n + 1) & 1) * 16384;
            const uint32_t Vn = Vs0 + (uint32_t)((n + 1) & 1) * 16384;
            const __nv_bfloat16* qsrc = qb + (size_t)(n + 1) * CHUNK * C_BOT;
            const __nv_bfloat16* vsrc = vb + (size_t)(n + 1) * CHUNK * C_BOT;
#pragma unroll
            for (int t = tid; t < 1024; t += 128) {
                const int r = t >> 4, u = t & 15;
                cp16(Qn + swz(r * 256 + u * 16), qsrc + (size_t)r * C_BOT + u * 8);
                cp16(Vn + swz(r * 256 + u * 16), vsrc + (size_t)r * C_BOT + u * 8);
            }
            CP_COMMIT();
        }

        // T = K . Q^T  (16 j x 64 i per warp); k pre-scaled by log2e
        float tacc[8][4];
#pragma unroll
        for (int n8 = 0; n8 < 8; n8++)
#pragma unroll
            for (int e = 0; e < 4; e++) tacc[n8][e] = 0.0f;
#pragma unroll
        for (int k = 0; k < 8; k++) {
#pragma unroll
            for (int n8p = 0; n8p < 4; n8p++) {
                uint32_t b[4];
                ldm_x4(b, Qc + swz((n8p * 16 + qrow) * 256 + k * 32 + qsel));
                mma16816(tacc[2 * n8p],     ka[k], b[0], b[1]);
                mma16816(tacc[2 * n8p + 1], ka[k], b[2], b[3]);
            }
        }

        // exp via ex2 (logits pre-scaled by log2e), rowsum, pack P
        uint32_t pa[4][4];
#pragma unroll
        for (int n8 = 0; n8 < 8; n8++) {
            const float e0 = ex2f(tacc[n8][0]);
            const float e1 = ex2f(tacc[n8][1]);
            const float e2 = ex2f(tacc[n8][2]);
            const float e3 = ex2f(tacc[n8][3]);
            l0 += e0 + e1;
            l1 += e2 + e3;
            const int s = n8 >> 1, h = (n8 & 1) * 2;
            pa[s][h]     = pk_bf16x2(e0, e1);
            pa[s][h + 1] = pk_bf16x2(e2, e3);
        }

        // O += P . V  (16 j x 128 c per warp)
#pragma unroll
        for (int s = 0; s < 4; s++) {
#pragma unroll
            for (int ctp = 0; ctp < 8; ctp++) {
                uint32_t b[4];
                ldm_x4t(b, Vc + swz((s * 16 + vrow) * 256 + ctp * 32 + vsel));
                mma16816(accO[2 * ctp],     pa[s], b[0], b[1]);
                mma16816(accO[2 * ctp + 1], pa[s], b[2], b[3]);
            }
        }
    }

    // epilogue: reduce l over quad, normalize, stage, write bf16
    l0 += __shfl_xor_sync(0xffffffffu, l0, 1);
    l0 += __shfl_xor_sync(0xffffffffu, l0, 2);
    l1 += __shfl_xor_sync(0xffffffffu, l1, 1);
    l1 += __shfl_xor_sync(0xffffffffu, l1, 2);
    const float inv0 = 1.0f / l0;
    const float inv1 = 1.0f / l1;

    __syncthreads();
    float* Os = (float*)sm;          // 64 x 128 fp32 staging (32KB)
    const int r0 = warp * 16 + g;
#pragma unroll
    for (int ct = 0; ct < 16; ct++) {
        *(float2*)&Os[r0 * 128 + ct * 8 + tig * 2] =
            make_float2(accO[ct][0] * inv0, accO[ct][1] * inv0);
        *(float2*)&Os[(r0 + 8) * 128 + ct * 8 + tig * 2] =
            make_float2(accO[ct][2] * inv1, accO[ct][3] * inv1);
    }
    __syncthreads();
#pragma unroll
    for (int t = tid; t < 64 * 16; t += 128) {
        const int r = t >> 4, c8 = t & 15;
        const float4 v0 = ((const float4*)(Os + r * 128))[c8 * 2];
        const float4 v1 = ((const float4*)(Os + r * 128))[c8 * 2 + 1];
        uint4 u;
        u.x = pk_bf16x2(v0.x, v0.y);
        u.y = pk_bf16x2(v0.z, v0.w);
        u.z = pk_bf16x2(v1.x, v1.y);
        u.w = pk_bf16x2(v1.z, v1.w);
        ((uint4*)(ob + (size_t)(j0 + r) * C_BOT))[c8] = u;
    }
}

// ---------------------------------------------------------------------------
// Fused QKV projection, all-bf16, cp.async double-buffered (round-7 proven).
// bk bias scaled by log2e to match pre-scaled Wk.
// ---------------------------------------------------------------------------
#define QKVB 32768

__global__ __launch_bounds__(128, 2)
void qkv_gemm(const __nv_bfloat16* __restrict__ Xb,
              const __nv_bfloat16* __restrict__ Wqb, const float* __restrict__ bq,
              const __nv_bfloat16* __restrict__ Wkb, const float* __restrict__ bk,
              const __nv_bfloat16* __restrict__ Wvb, const float* __restrict__ bv,
              __nv_bfloat16* __restrict__ qt, __nv_bfloat16* __restrict__ kt,
              __nv_bfloat16* __restrict__ vt)
{
    extern __shared__ char qsm[];
    const uint32_t sb = (uint32_t)__cvta_generic_to_shared(qsm);

    const int z  = blockIdx.z;
    const int m0 = blockIdx.y * 64;
    const int n0 = blockIdx.x * 64;
    const __nv_bfloat16* Xz = Xb + (size_t)z * C_IN * N_PIX;
    const __nv_bfloat16* Wp[3] = {Wqb, Wkb, Wvb};
    const float* bp[3] = {bq, bk, bv};
    __nv_bfloat16* outp[3] = {qt + (size_t)z * N_PIX * C_BOT,
                              kt + (size_t)z * N_PIX * C_BOT,
                              vt + (size_t)z * N_PIX * C_BOT};

    const int tid  = threadIdx.x;
    const int lane = tid & 31;
    const int warp = tid >> 5;
    const int g    = lane >> 2;
    const int tig  = lane & 3;

    auto prefetch = [&](int kc) {
        const uint32_t b = sb + (uint32_t)(kc & 1) * QKVB;
        const int k0 = kc * 64;
#pragma unroll
        for (int p = 0; p < 3; p++)
#pragma unroll
            for (int t = tid; t < 512; t += 128) {
                const int r = t >> 3, u = t & 7;
                cp16(b + p * 8192 + swz128(r * 128 + u * 16),
                     Wp[p] + (size_t)(m0 + r) * C_IN + k0 + u * 8);
            }
#pragma unroll
        for (int t = tid; t < 512; t += 128) {
            const int r = t >> 3, u = t & 7;
            cp16(b + 24576 + swz128(r * 128 + u * 16),
                 Xz + (size_t)(k0 + r) * N_PIX + n0 + u * 8);
        }
        CP_COMMIT();
    };

    prefetch(0);

    float acc[3][8][4];
#pragma unroll
    for (int p = 0; p < 3; p++)
#pragma unroll
        for (int n8 = 0; n8 < 8; n8++)
#pragma unroll
            for (int e = 0; e < 4; e++) acc[p][n8][e] = 0.0f;

    const uint32_t arow = (warp * 16 + (lane & 15)) * 128 + (((uint32_t)lane >> 4) & 1) * 16;
    const uint32_t xrow = (uint32_t)(lane & 15) * 128;
    const uint32_t xsel = (((uint32_t)lane >> 4) & 1) * 16;

    for (int kc = 0; kc < 4; kc++) {
        CP_WAIT0();
        __syncthreads();
        if (kc < 3) prefetch(kc + 1);

        const uint32_t W0 = sb + (uint32_t)(kc & 1) * QKVB;
        const uint32_t X0 = W0 + 24576;
#pragma unroll
        for (int ks = 0; ks < 4; ks++) {
            uint32_t a[3][4];
#pragma unroll
            for (int p = 0; p < 3; p++)
                ldm_x4(a[p], W0 + p * 8192 + swz128(arow + ks * 32));
#pragma unroll
            for (int n8p = 0; n8p < 4; n8p++) {
                uint32_t b[4];
                ldm_x4t(b, X0 + swz128((ks * 16) * 128 + xrow + n8p * 32 + xsel));
#pragma unroll
                for (int p = 0; p < 3; p++) {
                    mma16816(acc[p][2 * n8p],     a[p], b[0], b[1]);
                    mma16816(acc[p][2 * n8p + 1], a[p], b[2], b[3]);
                }
            }
        }
    }

    __syncthreads();
    float* Cs = (float*)qsm;   // [64][68]
#pragma unroll
    for (int p = 0; p < 3; p++) {
#pragma unroll
        for (int n8 = 0; n8 < 8; n8++) {
            const int rr = warp * 16 + g;
            const int cc = n8 * 8 + tig * 2;
            Cs[rr * 68 + cc]           = acc[p][n8][0];
            Cs[rr * 68 + cc + 1]       = acc[p][n8][1];
            Cs[(rr + 8) * 68 + cc]     = acc[p][n8][2];
            Cs[(rr + 8) * 68 + cc + 1] = acc[p][n8][3];
        }
        __syncthreads();
        const float bsc = (p == 1) ? LOG2E : 1.0f;
#pragma unroll 4
        for (int idx = tid; idx < 64 * 64; idx += 128) {
            const int r = idx & 63;   // m (channel)
            const int c = idx >> 6;   // n (pixel)
            const float v = Cs[r * 68 + c] + bp[p][m0 + r] * bsc;
            outp[p][(size_t)(n0 + c) * C_BOT + m0 + r] = __float2bfloat16(v);
        }
        __syncthreads();
    }
}

// ---------------------------------------------------------------------------
// Final projection (round-7 proven): y = gamma*(Wo . O + bo) + X.
// ---------------------------------------------------------------------------
__global__ __launch_bounds__(128)
void final_gemm(const __nv_bfloat16* __restrict__ Wob,
                const __nv_bfloat16* __restrict__ ot,
                float* __restrict__ out, const float* __restrict__ bo,
                const float* __restrict__ gammap, const float* __restrict__ X)
{
    __shared__ char buf[32768];
    const uint32_t sA = (uint32_t)__cvta_generic_to_shared(buf);
    const uint32_t sB = sA + 16384;
    float* Cs = (float*)buf;

    const int z  = blockIdx.z;
    const int o0 = blockIdx.y * 64;
    const int n0 = blockIdx.x * 64;
    const __nv_bfloat16* Ob = ot + (size_t)z * N_PIX * C_BOT;
    float* outb = out + (size_t)z * C_IN * N_PIX;
    const float* Xb = X + (size_t)z * C_IN * N_PIX;

    const int tid  = threadIdx.x;
    const int lane = tid & 31;
    const int warp = tid >> 5;
    const int wm = warp >> 1, wn = warp & 1;
    const int g  = lane >> 2, tig = lane & 3;

#pragma unroll
    for (int t = tid; t < 1024; t += 128) {
        const int r = t >> 4, u = t & 15;
        cp16(sA + swz(r * 256 + u * 16), Wob + (size_t)(o0 + r) * C_BOT + u * 8);
        cp16(sB + swz(r * 256 + u * 16), Ob + (size_t)(n0 + r) * C_BOT + u * 8);
    }
    CP_COMMIT();
    CP_WAIT0();
    __syncthreads();

    uint32_t a[2][8][4];
    {
        const uint32_t cb = (((uint32_t)lane >> 4) & 1) * 16;
#pragma unroll
        for (int im = 0; im < 2; im++)
#pragma unroll
            for (int ks = 0; ks < 8; ks++)
                ldm_x4(a[im][ks],
                       sA + swz((wm * 32 + im * 16 + (lane & 15)) * 256 + ks * 32 + cb));
    }

    float acc[2][4][4];
#pragma unroll
    for (int im = 0; im < 2; im++)
#pragma unroll
        for (int n8 = 0; n8 < 4; n8++)
#pragma unroll
            for (int e = 0; e < 4; e++) acc[im][n8][e] = 0.0f;

    {
        const uint32_t brow = (uint32_t)(lane & 15);
        const uint32_t bsel = (((uint32_t)lane >> 4) & 1) * 16;
#pragma unroll
        for (int ks = 0; ks < 8; ks++) {
#pragma unroll
            for (int n8p = 0; n8p < 2; n8p++) {
                uint32_t b[4];
                ldm_x4(b, sB + swz((wn * 32 + n8p * 16 + brow) * 256 + ks * 32 + bsel));
                mma16816(acc[0][2 * n8p],     a[0][ks], b[0], b[2]);
                mma16816(acc[0][2 * n8p + 1], a[0][ks], b[1], b[3]);
                mma16816(acc[1][2 * n8p],     a[1][ks], b[0], b[2]);
                mma16816(acc[1][2 * n8p + 1], a[1][ks], b[1], b[3]);
            }
        }
    }

    __syncthreads();
#pragma unroll
    for (int im = 0; im < 2; im++)
#pragma unroll
        for (int n8 = 0; n8 < 4; n8++) {
            const int rr = wm * 32 + im * 16 + g;
            const int cc = wn * 32 + n8 * 8 + tig * 2;
            Cs[rr * 68 + cc]           = acc[im][n8][0];
            Cs[rr * 68 + cc + 1]       = acc[im][n8][1];
            Cs[(rr + 8) * 68 + cc]     = acc[im][n8][2];
            Cs[(rr + 8) * 68 + cc + 1] = acc[im][n8][3];
        }
    __syncthreads();

    const float gm = gammap[0];
#pragma unroll
    for (int t = tid; t < 64 * 16; t += 128) {
        const int r = t >> 4, c4 = t & 15;
        const size_t off = (size_t)(o0 + r) * N_PIX + n0 + c4 * 4;
        const float4 xv = *(const float4*)&Xb[off];
        const float b = bo[o0 + r];
        float4 o;
        o.x = gm * (Cs[r * 68 + c4 * 4 + 0] + b) + xv.x;
        o.y = gm * (Cs[r * 68 + c4 * 4 + 1] + b) + xv.y;
        o.z = gm * (Cs[r * 68 + c4 * 4 + 2] + b) + xv.z;
        o.w = gm * (Cs[r * 68 + c4 * 4 + 3] + b) + xv.w;
        *(float4*)&outb[off] = o;
    }
}

extern "C" void kernel_launch(void* const* d_in, const int* in_sizes, int n_in,
                              void* d_out, int out_size)
{
    const float* X     = (const float*)d_in[0];
    const float* Wq    = (const float*)d_in[1];
    const float* bq    = (const float*)d_in[2];
    const float* Wk    = (const float*)d_in[3];
    const float* bk    = (const float*)d_in[4];
    const float* Wv    = (const float*)d_in[5];
    const float* bv    = (const float*)d_in[6];
    const float* Wo    = (const float*)d_in[7];
    const float* bo    = (const float*)d_in[8];
    const float* gamma = (const float*)d_in[9];
    float* out = (float*)d_out;

    __nv_bfloat16 *qt, *kt, *vt, *ot, *xb, *wq, *wk, *wv, *wo;
    cudaGetSymbolAddress((void**)&qt, g_qt);
    cudaGetSymbolAddress((void**)&kt, g_kt);
    cudaGetSymbolAddress((void**)&vt, g_vt);
    cudaGetSymbolAddress((void**)&ot, g_ot);
    cudaGetSymbolAddress((void**)&xb, g_xb);
    cudaGetSymbolAddress((void**)&wq, g_wq);
    cudaGetSymbolAddress((void**)&wk, g_wk);
    cudaGetSymbolAddress((void**)&wv, g_wv);
    cudaGetSymbolAddress((void**)&wo, g_wo);

    cudaFuncSetAttribute(flash_attn, cudaFuncAttributeMaxDynamicSharedMemorySize,
                         SMEM_FLASH);
    cudaFuncSetAttribute(qkv_gemm, cudaFuncAttributeMaxDynamicSharedMemorySize,
                         2 * QKVB);

    // 0) one-shot bf16 conversion of X and weights (Wk pre-scaled by log2e)
    convert_bf16<<<2048, 256>>>(X, Wq, Wk, Wv, Wo, xb, wq, wk, wv, wo);

    // 1) fused QKV -> transposed bf16 [n][c]
    qkv_gemm<<<dim3(N_PIX / 64, C_BOT / 64, NB), 128, 2 * QKVB>>>(
        xb, wq, bq, wk, bk, wv, bv, qt, kt, vt);

    // 2) fused attention -> ot bf16 [n][c]
    flash_attn<<<dim3(N_PIX / 64, NB), 128, SMEM_FLASH>>>(qt, kt, vt, ot);

    // 3) y = gamma*(Wo . O + bo) + X
    final_gemm<<<dim3(N_PIX / 64, C_IN / 64, NB), 128>>>(
        wo, ot, out, bo, gamma, X);
}